// round 1
// baseline (speedup 1.0000x reference)
#include <cuda_runtime.h>

#define N_NODES 8192
#define IN_DIM  256
#define OUT_DIM 128

// Scratch (device globals — no allocation allowed in kernel_launch)
__device__ float P_buf[N_NODES * OUT_DIM];  // g[j] * Wh[j][c]
__device__ float g_buf[N_NODES];            // exp(e[j])

// ---------------------------------------------------------------------------
// Phase 1: Wh = X @ W^T  (fused: e = relu(Wh)@a_w, g = exp(e), P = g*Wh)
// grid = 128 blocks (64 rows each), block = 256 threads (16x16 tiling)
// ---------------------------------------------------------------------------
__global__ __launch_bounds__(256)
void gat_phase1(const float* __restrict__ X,
                const float* __restrict__ W,
                const float* __restrict__ a_w)
{
    __shared__ float Xs[32][68];    // Xs[k][r] = X[r0+r][k0+k]
    __shared__ float Ws[32][132];   // Ws[k][c] = W[c][k0+k]
    __shared__ float aw_s[OUT_DIM];

    const int t  = threadIdx.x;
    const int tx = t & 15;
    const int ty = t >> 4;
    const int r0 = blockIdx.x * 64;

    if (t < OUT_DIM) aw_s[t] = a_w[t];

    float acc[4][8];
    #pragma unroll
    for (int r = 0; r < 4; r++)
        #pragma unroll
        for (int j = 0; j < 8; j++) acc[r][j] = 0.0f;

    for (int k0 = 0; k0 < IN_DIM; k0 += 32) {
        // load X tile (64 rows x 32 k), float4 global reads, transpose into smem
        {
            const int r = t >> 2, q = t & 3;
            #pragma unroll
            for (int it = 0; it < 2; it++) {
                const int f4 = q + 4 * it;
                float4 v = *reinterpret_cast<const float4*>(
                    &X[(r0 + r) * IN_DIM + k0 + 4 * f4]);
                Xs[4*f4+0][r] = v.x; Xs[4*f4+1][r] = v.y;
                Xs[4*f4+2][r] = v.z; Xs[4*f4+3][r] = v.w;
            }
        }
        // load W tile transposed: Ws[k][c] = W[c][k0+k]
        {
            const int k = t & 31, cb = t >> 5;
            #pragma unroll
            for (int it = 0; it < 16; it++) {
                const int c = cb + 8 * it;
                Ws[k][c] = W[c * IN_DIM + k0 + k];
            }
        }
        __syncthreads();

        #pragma unroll
        for (int k = 0; k < 32; k++) {
            float4 av = *reinterpret_cast<const float4*>(&Xs[k][4 * ty]);
            float ar[4] = {av.x, av.y, av.z, av.w};
            #pragma unroll
            for (int j = 0; j < 8; j++) {
                float b = Ws[k][tx + 16 * j];
                #pragma unroll
                for (int r = 0; r < 4; r++)
                    acc[r][j] = fmaf(ar[r], b, acc[r][j]);
            }
        }
        __syncthreads();
    }

    // Epilogue: e per row (reduce over the 16 tx lanes), g = exp(e), write P & g
    #pragma unroll
    for (int r = 0; r < 4; r++) {
        float ep = 0.0f;
        #pragma unroll
        for (int j = 0; j < 8; j++)
            ep = fmaf(fmaxf(acc[r][j], 0.0f), aw_s[tx + 16 * j], ep);
        // xor-reduce over tx bits (lanes 0..15 within each half-warp share ty)
        #pragma unroll
        for (int m = 8; m >= 1; m >>= 1)
            ep += __shfl_xor_sync(0xffffffffu, ep, m, 32);

        const float g  = expf(ep);
        const int row  = r0 + 4 * ty + r;
        #pragma unroll
        for (int j = 0; j < 8; j++)
            P_buf[row * OUT_DIM + tx + 16 * j] = g * acc[r][j];
        if (tx == 0) g_buf[row] = g;
    }
}

// ---------------------------------------------------------------------------
// Phase 2: h[i] = relu( (A @ P)[i] / (A @ g)[i] )
// M=8192, N=128 (+fused denominator), K=8192
// grid = 128 blocks (64 rows each), block = 256 threads.
// Thread tile: 4 rows x 8 cols, columns handled as 4 f32x2 pairs via
// packed fma.rn.f32x2 (FFMA2) for 2x fp32 FMA throughput.
// Column pairs are strided (pair index = tx + 16*j) so LDS.64 reads are
// conflict-free across the 16 tx lanes.
// ---------------------------------------------------------------------------
__global__ __launch_bounds__(256)
void gat_phase2(const float* __restrict__ A, float* __restrict__ out)
{
    __shared__ float As[32][68];    // As[k][r] = A[r0+r][k0+k]
    __shared__ float Ps[32][132];   // Ps[k][c] = P[k0+k][c]
    __shared__ float gs[32];

    const int t  = threadIdx.x;
    const int tx = t & 15;
    const int ty = t >> 4;
    const int r0 = blockIdx.x * 64;

    unsigned long long acc2[4][4];
    float den[4];
    #pragma unroll
    for (int r = 0; r < 4; r++) {
        den[r] = 0.0f;
        #pragma unroll
        for (int j = 0; j < 4; j++) acc2[r][j] = 0ULL;
    }

    for (int k0 = 0; k0 < N_NODES; k0 += 32) {
        // A tile (64 rows x 32 k): float4 reads, transposed scatter into smem
        {
            const int r = t >> 2, q = t & 3;
            #pragma unroll
            for (int it = 0; it < 2; it++) {
                const int f4 = q + 4 * it;
                float4 v = *reinterpret_cast<const float4*>(
                    &A[(size_t)(r0 + r) * N_NODES + k0 + 4 * f4]);
                As[4*f4+0][r] = v.x; As[4*f4+1][r] = v.y;
                As[4*f4+2][r] = v.z; As[4*f4+3][r] = v.w;
            }
        }
        // P tile (32 k x 128 c): float4 reads, direct float4 smem stores
        {
            const int c4 = t & 31, kb = t >> 5;
            #pragma unroll
            for (int it = 0; it < 4; it++) {
                const int k = kb + 8 * it;
                *reinterpret_cast<float4*>(&Ps[k][4 * c4]) =
                    *reinterpret_cast<const float4*>(&P_buf[(k0 + k) * OUT_DIM + 4 * c4]);
            }
        }
        if (t < 32) gs[t] = g_buf[k0 + t];
        __syncthreads();

        #pragma unroll
        for (int k = 0; k < 32; k++) {
            // 4 A-values for this thread's rows: one broadcast LDS.128
            float4 av = *reinterpret_cast<const float4*>(&As[k][4 * ty]);
            float ar[4] = {av.x, av.y, av.z, av.w};
            const float gk = gs[k];

            unsigned long long a2[4];
            #pragma unroll
            for (int r = 0; r < 4; r++) {
                asm("mov.b64 %0, {%1, %1};"
                    : "=l"(a2[r]) : "r"(__float_as_uint(ar[r])));
                den[r] = fmaf(ar[r], gk, den[r]);
            }

            const unsigned long long* prow =
                reinterpret_cast<const unsigned long long*>(&Ps[k][0]);
            #pragma unroll
            for (int j = 0; j < 4; j++) {
                unsigned long long p2 = prow[tx + 16 * j];   // LDS.64, conflict-free
                #pragma unroll
                for (int r = 0; r < 4; r++)
                    asm("fma.rn.f32x2 %0, %1, %2, %0;"
                        : "+l"(acc2[r][j]) : "l"(a2[r]), "l"(p2));
            }
        }
        __syncthreads();
    }

    // Epilogue: divide by denominator, relu, float2 stores
    #pragma unroll
    for (int r = 0; r < 4; r++) {
        const float inv = 1.0f / den[r];
        const int row = r0 + 4 * ty + r;
        #pragma unroll
        for (int j = 0; j < 4; j++) {
            unsigned lo, hi;
            asm("mov.b64 {%0, %1}, %2;" : "=r"(lo), "=r"(hi) : "l"(acc2[r][j]));
            float2 o;
            o.x = fmaxf(__uint_as_float(lo) * inv, 0.0f);
            o.y = fmaxf(__uint_as_float(hi) * inv, 0.0f);
            *reinterpret_cast<float2*>(&out[row * OUT_DIM + 2 * (tx + 16 * j)]) = o;
        }
    }
}

// ---------------------------------------------------------------------------
extern "C" void kernel_launch(void* const* d_in, const int* in_sizes, int n_in,
                              void* d_out, int out_size)
{
    const float* X   = (const float*)d_in[0];
    const float* A   = (const float*)d_in[1];
    const float* W   = (const float*)d_in[2];
    const float* a_w = (const float*)d_in[3];
    float* out = (float*)d_out;

    gat_phase1<<<N_NODES / 64, 256>>>(X, W, a_w);
    gat_phase2<<<N_NODES / 64, 256>>>(A, out);
}